// round 15
// baseline (speedup 1.0000x reference)
#include <cuda_runtime.h>
#include <cuda_bf16.h>
#include <cstdint>

#define HID 2048
#define MLP 8192
#define BATCH 256
#define NELEM_A (BATCH*HID)
#define NELEM_T (BATCH*MLP)
#define SROW 40
// per-tile byte sizes (CTA tile 128x64, BK=32)
#define STAGE_A_BYTES (2*128*SROW*2)    // Ah+Al per tile = 20480
#define ALO_BYTES     (128*SROW*2)      // 10240
#define WB_BYTES      (64*SROW*2)       // 5120 per W tile slot
#define LUT_BYTES     1024
// lut | 4 A tile stages | 4 W slots | 4x64 scales | mbarriers(32B)+pad
#define GEMM_SMEM (LUT_BYTES + 4*STAGE_A_BYTES + 4*WB_BYTES + 4*64*4 + 64)

__device__ __align__(16) __nv_bfloat16 g_a_hi[NELEM_A];
__device__ __align__(16) __nv_bfloat16 g_a_lo[NELEM_A];
__device__ __align__(16) __nv_bfloat16 g_t_hi[NELEM_T];
__device__ __align__(16) __nv_bfloat16 g_t_lo[NELEM_T];
__device__ __align__(16) float g_gate[NELEM_T];
__device__ __align__(16) float g_part[4*NELEM_A];

__device__ __forceinline__ uint32_t pack_bf2(__nv_bfloat16 a, __nv_bfloat16 b) {
    return (uint32_t)__bfloat16_as_ushort(a) | ((uint32_t)__bfloat16_as_ushort(b) << 16);
}
__device__ __forceinline__ float fp4_decode(int n) {
    int m = n & 7;
    float mag;
    if (m == 0) mag = 0.0f;
    else if (m == 1) mag = 0.5f;
    else mag = (1.0f + 0.5f * (float)(m & 1)) * (float)(1 << ((m >> 1) - 1));
    return (n & 8) ? -mag : mag;
}
__device__ __forceinline__ float silu_f(float v) { return v / (1.0f + __expf(-v)); }
__device__ __forceinline__ void mma_bf16(float* c, const uint32_t* a, const uint32_t* b) {
    asm volatile(
        "mma.sync.aligned.m16n8k16.row.col.f32.bf16.bf16.f32 "
        "{%0,%1,%2,%3}, {%4,%5,%6,%7}, {%8,%9}, {%0,%1,%2,%3};\n"
        : "+f"(c[0]), "+f"(c[1]), "+f"(c[2]), "+f"(c[3])
        : "r"(a[0]), "r"(a[1]), "r"(a[2]), "r"(a[3]), "r"(b[0]), "r"(b[1]));
}
__device__ __forceinline__ void ldsm4(uint32_t* r, uint32_t addr) {
    asm volatile("ldmatrix.sync.aligned.m8n8.x4.shared.b16 {%0,%1,%2,%3}, [%4];"
                 : "=r"(r[0]), "=r"(r[1]), "=r"(r[2]), "=r"(r[3]) : "r"(addr));
}
__device__ __forceinline__ void cp16(uint32_t dst, const void* src) {
    asm volatile("cp.async.cg.shared.global [%0], [%1], 16;" :: "r"(dst), "l"(src));
}
#define CP_COMMIT() asm volatile("cp.async.commit_group;" ::: "memory")
#define CP_WAIT1()  asm volatile("cp.async.wait_group 1;" ::: "memory")
#define CP_WAIT0()  asm volatile("cp.async.wait_group 0;" ::: "memory")

#define MBAR_INIT(a, c) \
    asm volatile("mbarrier.init.shared.b64 [%0], %1;" :: "r"(a), "r"(c) : "memory")
#define MBAR_ARRIVE(a) \
    asm volatile("mbarrier.arrive.release.cta.shared::cta.b64 _, [%0];" :: "r"(a) : "memory")
#define MBAR_WAIT(a, par) do { \
    uint32_t _m = (a), _p = (par), _d; \
    asm volatile("{\n\t.reg .pred p;\n\t" \
        "mbarrier.try_wait.parity.acquire.cta.shared::cta.b64 p, [%1], %2;\n\t" \
        "selp.b32 %0,1,0,p;\n\t}" : "=r"(_d) : "r"(_m), "r"(_p) : "memory"); \
    if (!_d) { \
        asm volatile("{\n\t.reg .pred P1;\n\t" \
            "WL_%=:\n\t" \
            "mbarrier.try_wait.parity.acquire.cta.shared::cta.b64 P1, [%0], %1, 0x989680;\n\t" \
            "@P1 bra.uni WD_%=;\n\tbra.uni WL_%=;\n\tWD_%=:\n\t}" \
            :: "r"(_m), "r"(_p) : "memory"); \
    } } while (0)

// GEMM: CTA tile 128(M) x 64(N), BK=32 (one scale block). 288 threads:
// warps 0-7 consumers (32x32 warp tiles), warp 8 producer (cp.async A ring,
// W LDG->LUT->STS exact-bf16 dequant, scale staging). mbarrier pair-slot ring
// (2 pair slots = 4 tile stages), NO __syncthreads in the main loop.
// Per-k-block fp32 scale folded post-MMA: acc += s[n]*part.
// mode 0: fp32 out (+ blockIdx.z*BATCH*ldN); mode 1: silu(gate)*acc -> bf16 hi/lo.
__global__ void __launch_bounds__(288, 2) gemm_kernel(
    const int* __restrict__ wp_base, const float* __restrict__ ws_base,
    const __nv_bfloat16* __restrict__ a_hi, const __nv_bfloat16* __restrict__ a_lo,
    float* __restrict__ out, int Ktot, int ldN, int mode,
    const float* __restrict__ gatebuf,
    __nv_bfloat16* __restrict__ t_hi, __nv_bfloat16* __restrict__ t_lo)
{
    extern __shared__ char smem[];
    uint32_t* lut = (uint32_t*)smem;                 // 256 x bf16x2 exact fp4 pairs
    char* ap  = smem + LUT_BYTES;                    // 4 A tile stages
    char* wbp = ap + 4*STAGE_A_BYTES;                // 4 W tile slots
    float* scb = (float*)(wbp + 4*WB_BYTES);         // 4 x 64 scales
    char* mbp = (char*)(scb + 4*64);                 // 4 mbarriers
    const uint32_t ap_u = (uint32_t)__cvta_generic_to_shared(ap);
    const uint32_t wb_u = (uint32_t)__cvta_generic_to_shared(wbp);
    const uint32_t mb_u = (uint32_t)__cvta_generic_to_shared(mbp);
    // full[s] = mb_u + s*8 ; empty[s] = mb_u + 16 + s*8

    const int tid = threadIdx.x;
    const int warp = tid >> 5, lane = tid & 31;
    const int n0 = blockIdx.x * 64;
    const int m0 = blockIdx.y * 128;
    const int klen = Ktot / gridDim.z;
    const int kb = blockIdx.z * klen;
    const int npair = klen >> 6;              // 32 pairs (64 k-tiles)

    if (tid < 256)
        lut[tid] = pack_bf2(__float2bfloat16(fp4_decode(tid & 15)),
                            __float2bfloat16(fp4_decode(tid >> 4)));
    if (tid == 0) {
        MBAR_INIT(mb_u + 0, 1);   // full0  (producer lane 0 arrives)
        MBAR_INIT(mb_u + 8, 1);   // full1
        MBAR_INIT(mb_u + 16, 8);  // empty0 (one arrive per consumer warp)
        MBAR_INIT(mb_u + 24, 8);  // empty1
    }
    __syncthreads();   // lut + barriers visible; ONLY CTA-wide sync in the kernel

    if (warp == 8) {
        // ---------------- producer warp ----------------
        const int lr = lane >> 2, lc = lane & 3;
        const __nv_bfloat16* pAh = a_hi + (size_t)(m0 + lr) * Ktot + kb + lc * 8;
        const __nv_bfloat16* pAl = a_lo + (size_t)(m0 + lr) * Ktot + kb + lc * 8;
        const uint32_t dA = (uint32_t)(lr * SROW + lc * 8) * 2;
        const int* pW0 = wp_base + (size_t)(n0 + lane) * (Ktot >> 1) + (kb >> 1);
        const int* pW1 = wp_base + (size_t)(n0 + lane + 32) * (Ktot >> 1) + (kb >> 1);
        const float* pS0 = ws_base + (size_t)(n0 + lane) * (Ktot >> 5) + (kb >> 5);
        const float* pS1 = ws_base + (size_t)(n0 + lane + 32) * (Ktot >> 5) + (kb >> 5);

        for (int j = 0; j < npair; ++j) {
            if (j >= 2) MBAR_WAIT(mb_u + 16 + (j & 1) * 8, ((j >> 1) - 1) & 1);
            // A cp.async for tiles 2j, 2j+1
#pragma unroll
            for (int h = 0; h < 2; ++h) {
                const int t = 2 * j + h;
                const uint32_t sb = ap_u + (uint32_t)(t & 3) * STAGE_A_BYTES;
                const int koff = t * 32;
#pragma unroll
                for (int i = 0; i < 16; ++i) {
                    const uint32_t dd = dA + (uint32_t)(i * 8 * SROW * 2);
                    const size_t so = (size_t)(i * 8) * Ktot + koff;
                    cp16(sb + dd, pAh + so);
                    cp16(sb + (uint32_t)ALO_BYTES + dd, pAl + so);
                }
            }
            CP_COMMIT();
            if (j > 0) {
                CP_WAIT1();          // pair j-1 A data landed (this lane's)
                __syncwarp();        // order ALL lanes' cp.async + prior W STS
                if (lane == 0) MBAR_ARRIVE(mb_u + ((j - 1) & 1) * 8);
            }
            // W + scales for tiles 2j, 2j+1 (slots guarded by the empty wait above)
#pragma unroll
            for (int h = 0; h < 2; ++h) {
                const int t = 2 * j + h;
                const uint32_t ws = (uint32_t)(t & 3);
                char* wdst = wbp + ws * WB_BYTES;
#pragma unroll
                for (int rr = 0; rr < 2; ++rr) {
                    const int* src = (rr ? pW1 : pW0) + t * 16;
                    char* drow = wdst + ((rr ? lane + 32 : lane) * SROW) * 2;
#pragma unroll
                    for (int c4 = 0; c4 < 4; ++c4) {
                        int4 w = *(const int4*)(src + c4 * 4);
                        *(uint4*)(drow + c4 * 16) =
                            make_uint4(lut[w.x & 255], lut[w.y & 255],
                                       lut[w.z & 255], lut[w.w & 255]);
                    }
                }
                scb[ws * 64 + lane]      = pS0[t];
                scb[ws * 64 + lane + 32] = pS1[t];
            }
        }
        CP_WAIT0();
        __syncwarp();
        if (lane == 0) MBAR_ARRIVE(mb_u + ((npair - 1) & 1) * 8);
    } else {
        // ---------------- consumer warps (0-7) ----------------
        const int wm = warp >> 1, wnw = warp & 1;
        const int g = lane >> 2, tt = lane & 3;
        const uint32_t a_off = (uint32_t)(((wm*32 + (lane & 15))*SROW + (lane >> 4)*8) * 2);
        const uint32_t b_off = (uint32_t)(((wnw*32 + ((lane >> 4) << 3) + (lane & 7))*SROW
                                          + ((lane >> 3) & 1)*8) * 2);
        const int sc_idx = wnw*32 + 2*tt;

        float acc[32];
#pragma unroll
        for (int i = 0; i < 32; ++i) acc[i] = 0.f;

        for (int j = 0; j < npair; ++j) {
            MBAR_WAIT(mb_u + (j & 1) * 8, (j >> 1) & 1);
#pragma unroll
            for (int h = 0; h < 2; ++h) {
                const int t = 2 * j + h;
                const uint32_t u   = ap_u + (uint32_t)(t & 3) * STAGE_A_BYTES;
                const uint32_t wbu = wb_u + (uint32_t)(t & 3) * WB_BYTES;
                float part[32];
#pragma unroll
                for (int i = 0; i < 32; ++i) part[i] = 0.f;
#pragma unroll
                for (int ks = 0; ks < 2; ++ks) {
                    const uint32_t kso = (uint32_t)(ks*16*2);
                    uint32_t ah[2][4], al[2][4];
#pragma unroll
                    for (int mi = 0; mi < 2; ++mi) {
                        const uint32_t mo = (uint32_t)(mi*16*SROW*2);
                        ldsm4(ah[mi], u + a_off + mo + kso);
                        ldsm4(al[mi], u + (uint32_t)ALO_BYTES + a_off + mo + kso);
                    }
                    uint32_t bw[2][4];
#pragma unroll
                    for (int gb = 0; gb < 2; ++gb) {
                        const uint32_t go = (uint32_t)(gb*16*SROW*2);
                        ldsm4(bw[gb], wbu + b_off + go + kso);
                    }
#pragma unroll
                    for (int ni = 0; ni < 4; ++ni) {
                        const uint32_t* pb = &bw[ni >> 1][(ni & 1)*2];
#pragma unroll
                        for (int mi = 0; mi < 2; ++mi) {
                            float* pp = part + mi*16 + ni*4;
                            mma_bf16(pp, ah[mi], pb);   // Ah * W
                            mma_bf16(pp, al[mi], pb);   // Al * W
                        }
                    }
                }
                const float* scp = scb + (t & 3)*64;
#pragma unroll
                for (int ni = 0; ni < 4; ++ni) {
                    float2 sv = *(const float2*)(scp + sc_idx + ni*8);
#pragma unroll
                    for (int mi = 0; mi < 2; ++mi) {
                        float* c = acc + mi*16 + ni*4;
                        const float* pp = part + mi*16 + ni*4;
                        c[0] = fmaf(sv.x, pp[0], c[0]);
                        c[1] = fmaf(sv.y, pp[1], c[1]);
                        c[2] = fmaf(sv.x, pp[2], c[2]);
                        c[3] = fmaf(sv.y, pp[3], c[3]);
                    }
                }
            }
            __syncwarp();   // all lanes' slot reads done before releasing the slot
            if (lane == 0) MBAR_ARRIVE(mb_u + 16 + (j & 1) * 8);
        }

        // -------- epilogue (consumers only) --------
        if (mode == 1) {
#pragma unroll
            for (int mi = 0; mi < 2; ++mi)
#pragma unroll
                for (int ni = 0; ni < 4; ++ni) {
                    const float* c = acc + mi*16 + ni*4;
                    int r0 = m0 + wm*32 + mi*16 + g;
                    int jj = n0 + wnw*32 + ni*8 + 2*tt;
                    {
                        float t0 = silu_f(gatebuf[(size_t)r0*ldN + jj])     * c[0];
                        float t1 = silu_f(gatebuf[(size_t)r0*ldN + jj + 1]) * c[1];
                        __nv_bfloat16 h0 = __float2bfloat16(t0), h1 = __float2bfloat16(t1);
                        *(uint32_t*)(t_hi + (size_t)r0*ldN + jj) = pack_bf2(h0, h1);
                        *(uint32_t*)(t_lo + (size_t)r0*ldN + jj) =
                            pack_bf2(__float2bfloat16(t0 - __bfloat162float(h0)),
                                     __float2bfloat16(t1 - __bfloat162float(h1)));
                    }
                    {
                        int r1 = r0 + 8;
                        float t2 = silu_f(gatebuf[(size_t)r1*ldN + jj])     * c[2];
                        float t3 = silu_f(gatebuf[(size_t)r1*ldN + jj + 1]) * c[3];
                        __nv_bfloat16 h2 = __float2bfloat16(t2), h3 = __float2bfloat16(t3);
                        *(uint32_t*)(t_hi + (size_t)r1*ldN + jj) = pack_bf2(h2, h3);
                        *(uint32_t*)(t_lo + (size_t)r1*ldN + jj) =
                            pack_bf2(__float2bfloat16(t2 - __bfloat162float(h2)),
                                     __float2bfloat16(t3 - __bfloat162float(h3)));
                    }
                }
        } else {
            float* po = out + (size_t)blockIdx.z * BATCH * ldN;
#pragma unroll
            for (int mi = 0; mi < 2; ++mi)
#pragma unroll
                for (int ni = 0; ni < 4; ++ni) {
                    const float* c = acc + mi*16 + ni*4;
                    int r0 = m0 + wm*32 + mi*16 + g;
                    int jj = n0 + wnw*32 + ni*8 + 2*tt;
                    *(float2*)(po + (size_t)r0*ldN + jj)     = make_float2(c[0], c[1]);
                    *(float2*)(po + (size_t)(r0+8)*ldN + jj) = make_float2(c[2], c[3]);
                }
        }
    }
}

__global__ void split_x_kernel(const float* __restrict__ x) {
    int i = blockIdx.x * 256 + threadIdx.x;
    float v = x[i];
    __nv_bfloat16 h = __float2bfloat16(v);
    g_a_hi[i] = h;
    g_a_lo[i] = __float2bfloat16(v - __bfloat162float(h));
}

__global__ void reduce_split_kernel(float* __restrict__ out, int final_layer) {
    int i = blockIdx.x * 256 + threadIdx.x;
    float s = g_part[i] + g_part[i + NELEM_A] + g_part[i + 2*NELEM_A] + g_part[i + 3*NELEM_A];
    if (final_layer) {
        out[i] = s;
    } else {
        __nv_bfloat16 h = __float2bfloat16(s);
        g_a_hi[i] = h;
        g_a_lo[i] = __float2bfloat16(s - __bfloat162float(h));
    }
}

extern "C" void kernel_launch(void* const* d_in, const int* in_sizes, int n_in,
                              void* d_out, int out_size) {
    const float* x  = (const float*)d_in[0];
    const int*   gp = (const int*)d_in[1];
    const float* gs = (const float*)d_in[2];
    const int*   up = (const int*)d_in[3];
    const float* us = (const float*)d_in[4];
    const int*   dp = (const int*)d_in[5];
    const float* ds = (const float*)d_in[6];
    float* out = (float*)d_out;

    cudaFuncSetAttribute(gemm_kernel, cudaFuncAttributeMaxDynamicSharedMemorySize, GEMM_SMEM);

    void *p_ah, *p_al, *p_th, *p_tl, *p_g, *p_part;
    cudaGetSymbolAddress(&p_ah, g_a_hi);
    cudaGetSymbolAddress(&p_al, g_a_lo);
    cudaGetSymbolAddress(&p_th, g_t_hi);
    cudaGetSymbolAddress(&p_tl, g_t_lo);
    cudaGetSymbolAddress(&p_g, g_gate);
    cudaGetSymbolAddress(&p_part, g_part);

    split_x_kernel<<<NELEM_A/256, 256>>>(x);

    for (int l = 0; l < 18; ++l) {
        const size_t woff  = (size_t)l * MLP * (HID/2);
        const size_t soff  = (size_t)l * MLP * (HID/32);
        const size_t dwoff = (size_t)l * HID * (MLP/2);
        const size_t dsoff = (size_t)l * HID * (MLP/32);

        gemm_kernel<<<dim3(MLP/64, 2, 1), 288, GEMM_SMEM>>>(
            gp + woff, gs + soff,
            (const __nv_bfloat16*)p_ah, (const __nv_bfloat16*)p_al,
            (float*)p_g, HID, MLP, 0, nullptr, nullptr, nullptr);
        gemm_kernel<<<dim3(MLP/64, 2, 1), 288, GEMM_SMEM>>>(
            up + woff, us + soff,
            (const __nv_bfloat16*)p_ah, (const __nv_bfloat16*)p_al,
            nullptr, HID, MLP, 1, (const float*)p_g,
            (__nv_bfloat16*)p_th, (__nv_bfloat16*)p_tl);
        gemm_kernel<<<dim3(HID/64, 2, 4), 288, GEMM_SMEM>>>(
            dp + dwoff, ds + dsoff,
            (const __nv_bfloat16*)p_th, (const __nv_bfloat16*)p_tl,
            (float*)p_part, MLP, HID, 0, nullptr, nullptr, nullptr);
        reduce_split_kernel<<<NELEM_A/256, 256>>>(out, l == 17 ? 1 : 0);
    }
}

// round 16
// speedup vs baseline: 1.5414x; 1.5414x over previous
#include <cuda_runtime.h>
#include <cuda_bf16.h>
#include <cstdint>

#define HID 2048
#define MLP 8192
#define BATCH 256
#define NELEM_A (BATCH*HID)
#define NELEM_T (BATCH*MLP)
#define SROW 40
// byte sizes (CTA tile 128x128, BK=32)
#define STAGE_A_BYTES (2*128*SROW*2)    // Ah+Al per tile = 20480
#define ALO_BYTES     (128*SROW*2)      // 10240
#define WB_BYTES      (128*SROW*2)      // 10240 per W tile slot (128 rows)
#define LUT_BYTES     1024
// lut | 4 A tile stages | 4 W slots | 4 x 128 scale floats
#define GEMM_SMEM (LUT_BYTES + 4*STAGE_A_BYTES + 4*WB_BYTES + 4*128*4)

__device__ __align__(16) __nv_bfloat16 g_a_hi[NELEM_A];
__device__ __align__(16) __nv_bfloat16 g_a_lo[NELEM_A];
__device__ __align__(16) __nv_bfloat16 g_t_hi[NELEM_T];
__device__ __align__(16) __nv_bfloat16 g_t_lo[NELEM_T];
__device__ __align__(16) float g_gate[NELEM_T];
__device__ __align__(16) float g_part[4*NELEM_A];

__device__ __forceinline__ uint32_t pack_bf2(__nv_bfloat16 a, __nv_bfloat16 b) {
    return (uint32_t)__bfloat16_as_ushort(a) | ((uint32_t)__bfloat16_as_ushort(b) << 16);
}
__device__ __forceinline__ float fp4_decode(int n) {
    int m = n & 7;
    float mag;
    if (m == 0) mag = 0.0f;
    else if (m == 1) mag = 0.5f;
    else mag = (1.0f + 0.5f * (float)(m & 1)) * (float)(1 << ((m >> 1) - 1));
    return (n & 8) ? -mag : mag;
}
__device__ __forceinline__ float silu_f(float v) { return v / (1.0f + __expf(-v)); }
__device__ __forceinline__ void mma_bf16(float* c, const uint32_t* a, const uint32_t* b) {
    asm volatile(
        "mma.sync.aligned.m16n8k16.row.col.f32.bf16.bf16.f32 "
        "{%0,%1,%2,%3}, {%4,%5,%6,%7}, {%8,%9}, {%0,%1,%2,%3};\n"
        : "+f"(c[0]), "+f"(c[1]), "+f"(c[2]), "+f"(c[3])
        : "r"(a[0]), "r"(a[1]), "r"(a[2]), "r"(a[3]), "r"(b[0]), "r"(b[1]));
}
__device__ __forceinline__ void ldsm4(uint32_t* r, uint32_t addr) {
    asm volatile("ldmatrix.sync.aligned.m8n8.x4.shared.b16 {%0,%1,%2,%3}, [%4];"
                 : "=r"(r[0]), "=r"(r[1]), "=r"(r[2]), "=r"(r[3]) : "r"(addr));
}
__device__ __forceinline__ void cp16(uint32_t dst, const void* src) {
    asm volatile("cp.async.cg.shared.global [%0], [%1], 16;" :: "r"(dst), "l"(src));
}
#define CP_COMMIT() asm volatile("cp.async.commit_group;" ::: "memory")
#define CP_WAIT0()  asm volatile("cp.async.wait_group 0;" ::: "memory")

// GEMM: CTA tile 128(M) x 128(N), BK=32 (one scale block). 512 threads (16 warps,
// 4x4 warp grid of 32x32 warp tiles), 1 CTA/SM. Pairwise pipeline: 2 k-tiles per
// iteration, ONE barrier + ONE cp.async wait per pair. A: 4-stage cp.async ring;
// W: exact-bf16 LUT dequant, 4-slot ring staged one pair ahead (threads 0-127).
// Per-k-block fp32 scale folded post-MMA: acc += s[n]*part.
// mode 0: fp32 out (+ blockIdx.z*BATCH*ldN); mode 1: silu(gate)*acc -> bf16 hi/lo.
__global__ void __launch_bounds__(512, 1) gemm_kernel(
    const int* __restrict__ wp_base, const float* __restrict__ ws_base,
    const __nv_bfloat16* __restrict__ a_hi, const __nv_bfloat16* __restrict__ a_lo,
    float* __restrict__ out, int Ktot, int ldN, int mode,
    const float* __restrict__ gatebuf,
    __nv_bfloat16* __restrict__ t_hi, __nv_bfloat16* __restrict__ t_lo)
{
    extern __shared__ char smem[];
    uint32_t* lut = (uint32_t*)smem;                 // 256 x bf16x2 exact fp4 pairs
    char* ringp = smem + LUT_BYTES;                  // 4 A tile stages
    char* wbp   = ringp + 4*STAGE_A_BYTES;           // 4 W tile slots (128 rows)
    float* scb  = (float*)(wbp + 4*WB_BYTES);        // 4 x 128 scales
    const uint32_t ring_u = (uint32_t)__cvta_generic_to_shared(ringp);
    const uint32_t wb_u   = (uint32_t)__cvta_generic_to_shared(wbp);

    const int tid = threadIdx.x;
    const int n0 = blockIdx.x * 128;
    const int m0 = blockIdx.y * 128;
    const int klen = Ktot / gridDim.z;
    const int kb = blockIdx.z * klen;
    const int npair = klen >> 6;              // 32 pairs (64 k-tiles) all configs
    if (tid < 256)
        lut[tid] = pack_bf2(__float2bfloat16(fp4_decode(tid & 15)),
                            __float2bfloat16(fp4_decode(tid >> 4)));

    // A staging map: row r = tid>>2 (0..127), 16B chunk q = tid&3 (hi + lo)
    const int r = tid >> 2, q = tid & 3;
    const __nv_bfloat16* gAh = a_hi + (size_t)(m0 + r) * Ktot + kb + q * 8;
    const __nv_bfloat16* gAl = a_lo + (size_t)(m0 + r) * Ktot + kb + q * 8;
    const uint32_t dA = (uint32_t)(r * SROW + q * 8) * 2;

    // W map: threads 0-127, one row each; per tile one int4 (32 fp4 = 64B bf16)
    const bool wact = tid < 128;
    const int* wp = wp_base + (size_t)(n0 + tid) * (Ktot >> 1) + (kb >> 1);
    const float* wsp = ws_base + (size_t)(n0 + tid) * (Ktot >> 5) + (kb >> 5);
    const uint32_t wdst = (uint32_t)(tid * SROW) * 2;

    const int warp = tid >> 5, lane = tid & 31;
    const int wm = warp >> 2, wnw = warp & 3;        // 4x4 warp grid
    const int g = lane >> 2, tt = lane & 3;
    const uint32_t a_off = (uint32_t)(((wm*32 + (lane & 15))*SROW + (lane >> 4)*8) * 2);
    const uint32_t b_off = (uint32_t)(((wnw*32 + ((lane >> 4) << 3) + (lane & 7))*SROW
                                      + ((lane >> 3) & 1)*8) * 2);
    const int sc_idx = wnw*32 + 2*tt;

    float acc[32];
#pragma unroll
    for (int i = 0; i < 32; ++i) acc[i] = 0.f;

    // ---- prologue ----
#pragma unroll
    for (int t = 0; t < 2; ++t) {
        const uint32_t sb = ring_u + (uint32_t)t * STAGE_A_BYTES;
        const int off = t * 32;
        cp16(sb + dA, gAh + off);
        cp16(sb + (uint32_t)ALO_BYTES + dA, gAl + off);
    }
    CP_COMMIT();
    // W regs: pair 0 (tiles 0,1) now, pair 1 (tiles 2,3) held
    int4 wv0 = {0,0,0,0}, wv1 = {0,0,0,0}, wh0 = {0,0,0,0}, wh1 = {0,0,0,0};
    float sv0 = 0.f, sv1 = 0.f, sh0 = 0.f, sh1 = 0.f;
    if (wact) {
        wv0 = *(const int4*)wp;          sv0 = wsp[0];
        wv1 = *(const int4*)(wp + 4);    sv1 = wsp[1];
        wh0 = *(const int4*)(wp + 8);    sh0 = wsp[2];
        wh1 = *(const int4*)(wp + 12);   sh1 = wsp[3];
    }

    __syncthreads();   // lut visible
    if (wact) {
        char* w0 = wbp + 0*WB_BYTES + wdst;
        char* w1 = wbp + 1*WB_BYTES + wdst;
        *(uint4*)(w0)      = make_uint4(lut[wv0.x & 255], lut[(wv0.x >> 8) & 255],
                                        lut[(wv0.x >> 16) & 255], lut[(wv0.x >> 24) & 255]);
        *(uint4*)(w0 + 16) = make_uint4(lut[wv0.y & 255], lut[(wv0.y >> 8) & 255],
                                        lut[(wv0.y >> 16) & 255], lut[(wv0.y >> 24) & 255]);
        *(uint4*)(w0 + 32) = make_uint4(lut[wv0.z & 255], lut[(wv0.z >> 8) & 255],
                                        lut[(wv0.z >> 16) & 255], lut[(wv0.z >> 24) & 255]);
        *(uint4*)(w0 + 48) = make_uint4(lut[wv0.w & 255], lut[(wv0.w >> 8) & 255],
                                        lut[(wv0.w >> 16) & 255], lut[(wv0.w >> 24) & 255]);
        *(uint4*)(w1)      = make_uint4(lut[wv1.x & 255], lut[(wv1.x >> 8) & 255],
                                        lut[(wv1.x >> 16) & 255], lut[(wv1.x >> 24) & 255]);
        *(uint4*)(w1 + 16) = make_uint4(lut[wv1.y & 255], lut[(wv1.y >> 8) & 255],
                                        lut[(wv1.y >> 16) & 255], lut[(wv1.y >> 24) & 255]);
        *(uint4*)(w1 + 32) = make_uint4(lut[wv1.z & 255], lut[(wv1.z >> 8) & 255],
                                        lut[(wv1.z >> 16) & 255], lut[(wv1.z >> 24) & 255]);
        *(uint4*)(w1 + 48) = make_uint4(lut[wv1.w & 255], lut[(wv1.w >> 8) & 255],
                                        lut[(wv1.w >> 16) & 255], lut[(wv1.w >> 24) & 255]);
        scb[0*128 + tid] = sv0;
        scb[1*128 + tid] = sv1;
    }

    for (int p = 0; p < npair; ++p) {
        CP_WAIT0();
        __syncthreads();    // A pair p arrived; W slots (pair p) staged; prev reads done
        // issue A pair p+1 + stage W pair p+1 (slots last read at iter p-1)
        if (p + 1 < npair) {
#pragma unroll
            for (int h = 0; h < 2; ++h) {
                const int t = 2*p + 2 + h;
                const uint32_t sb = ring_u + (uint32_t)(t & 3) * STAGE_A_BYTES;
                const int off = t * 32;
                cp16(sb + dA, gAh + off);
                cp16(sb + (uint32_t)ALO_BYTES + dA, gAl + off);
            }
            if (wact) {
                char* w0 = wbp + (uint32_t)((2*p+2) & 3)*WB_BYTES + wdst;
                char* w1 = wbp + (uint32_t)((2*p+3) & 3)*WB_BYTES + wdst;
                *(uint4*)(w0)      = make_uint4(lut[wh0.x & 255], lut[(wh0.x >> 8) & 255],
                                                lut[(wh0.x >> 16) & 255], lut[(wh0.x >> 24) & 255]);
                *(uint4*)(w0 + 16) = make_uint4(lut[wh0.y & 255], lut[(wh0.y >> 8) & 255],
                                                lut[(wh0.y >> 16) & 255], lut[(wh0.y >> 24) & 255]);
                *(uint4*)(w0 + 32) = make_uint4(lut[wh0.z & 255], lut[(wh0.z >> 8) & 255],
                                                lut[(wh0.z >> 16) & 255], lut[(wh0.z >> 24) & 255]);
                *(uint4*)(w0 + 48) = make_uint4(lut[wh0.w & 255], lut[(wh0.w >> 8) & 255],
                                                lut[(wh0.w >> 16) & 255], lut[(wh0.w >> 24) & 255]);
                *(uint4*)(w1)      = make_uint4(lut[wh1.x & 255], lut[(wh1.x >> 8) & 255],
                                                lut[(wh1.x >> 16) & 255], lut[(wh1.x >> 24) & 255]);
                *(uint4*)(w1 + 16) = make_uint4(lut[wh1.y & 255], lut[(wh1.y >> 8) & 255],
                                                lut[(wh1.y >> 16) & 255], lut[(wh1.y >> 24) & 255]);
                *(uint4*)(w1 + 32) = make_uint4(lut[wh1.z & 255], lut[(wh1.z >> 8) & 255],
                                                lut[(wh1.z >> 16) & 255], lut[(wh1.z >> 24) & 255]);
                *(uint4*)(w1 + 48) = make_uint4(lut[wh1.w & 255], lut[(wh1.w >> 8) & 255],
                                                lut[(wh1.w >> 16) & 255], lut[(wh1.w >> 24) & 255]);
                scb[((2*p+2) & 3)*128 + tid] = sh0;
                scb[((2*p+3) & 3)*128 + tid] = sh1;
            }
        }
        CP_COMMIT();
        // prefetch W pair p+2
        if (wact && p + 2 < npair) {
            wh0 = *(const int4*)(wp + (2*p + 4) * 4);  sh0 = wsp[2*p + 4];
            wh1 = *(const int4*)(wp + (2*p + 5) * 4);  sh1 = wsp[2*p + 5];
        }

        // compute tiles 2p and 2p+1
#pragma unroll
        for (int h = 0; h < 2; ++h) {
            const int t = 2*p + h;
            const uint32_t u   = ring_u + (uint32_t)(t & 3) * STAGE_A_BYTES;
            const uint32_t wbu = wb_u + (uint32_t)(t & 3) * WB_BYTES;
            float part[32];
#pragma unroll
            for (int i = 0; i < 32; ++i) part[i] = 0.f;
#pragma unroll
            for (int ks = 0; ks < 2; ++ks) {
                const uint32_t kso = (uint32_t)(ks*16*2);
                uint32_t ah[2][4], al[2][4];
#pragma unroll
                for (int mi = 0; mi < 2; ++mi) {
                    const uint32_t mo = (uint32_t)(mi*16*SROW*2);
                    ldsm4(ah[mi], u + a_off + mo + kso);
                    ldsm4(al[mi], u + (uint32_t)ALO_BYTES + a_off + mo + kso);
                }
                uint32_t bw[2][4];
#pragma unroll
                for (int gb = 0; gb < 2; ++gb) {
                    const uint32_t go = (uint32_t)(gb*16*SROW*2);
                    ldsm4(bw[gb], wbu + b_off + go + kso);
                }
#pragma unroll
                for (int ni = 0; ni < 4; ++ni) {
                    const uint32_t* pb = &bw[ni >> 1][(ni & 1)*2];
#pragma unroll
                    for (int mi = 0; mi < 2; ++mi) {
                        float* pp = part + mi*16 + ni*4;
                        mma_bf16(pp, ah[mi], pb);   // Ah * W
                        mma_bf16(pp, al[mi], pb);   // Al * W
                    }
                }
            }
            const float* scp = scb + (t & 3)*128;
#pragma unroll
            for (int ni = 0; ni < 4; ++ni) {
                float2 sv = *(const float2*)(scp + sc_idx + ni*8);
#pragma unroll
                for (int mi = 0; mi < 2; ++mi) {
                    float* c = acc + mi*16 + ni*4;
                    const float* pp = part + mi*16 + ni*4;
                    c[0] = fmaf(sv.x, pp[0], c[0]);
                    c[1] = fmaf(sv.y, pp[1], c[1]);
                    c[2] = fmaf(sv.x, pp[2], c[2]);
                    c[3] = fmaf(sv.y, pp[3], c[3]);
                }
            }
        }
        if (wact) { wv0 = wh0; wv1 = wh1; sv0 = sh0; sv1 = sh1; }
    }

    if (mode == 1) {
#pragma unroll
        for (int mi = 0; mi < 2; ++mi)
#pragma unroll
            for (int ni = 0; ni < 4; ++ni) {
                const float* c = acc + mi*16 + ni*4;
                int r0 = m0 + wm*32 + mi*16 + g;
                int jj = n0 + wnw*32 + ni*8 + 2*tt;
                {
                    float t0 = silu_f(gatebuf[(size_t)r0*ldN + jj])     * c[0];
                    float t1 = silu_f(gatebuf[(size_t)r0*ldN + jj + 1]) * c[1];
                    __nv_bfloat16 h0 = __float2bfloat16(t0), h1 = __float2bfloat16(t1);
                    *(uint32_t*)(t_hi + (size_t)r0*ldN + jj) = pack_bf2(h0, h1);
                    *(uint32_t*)(t_lo + (size_t)r0*ldN + jj) =
                        pack_bf2(__float2bfloat16(t0 - __bfloat162float(h0)),
                                 __float2bfloat16(t1 - __bfloat162float(h1)));
                }
                {
                    int r1 = r0 + 8;
                    float t2 = silu_f(gatebuf[(size_t)r1*ldN + jj])     * c[2];
                    float t3 = silu_f(gatebuf[(size_t)r1*ldN + jj + 1]) * c[3];
                    __nv_bfloat16 h2 = __float2bfloat16(t2), h3 = __float2bfloat16(t3);
                    *(uint32_t*)(t_hi + (size_t)r1*ldN + jj) = pack_bf2(h2, h3);
                    *(uint32_t*)(t_lo + (size_t)r1*ldN + jj) =
                        pack_bf2(__float2bfloat16(t2 - __bfloat162float(h2)),
                                 __float2bfloat16(t3 - __bfloat162float(h3)));
                }
            }
    } else {
        float* po = out + (size_t)blockIdx.z * BATCH * ldN;
#pragma unroll
        for (int mi = 0; mi < 2; ++mi)
#pragma unroll
            for (int ni = 0; ni < 4; ++ni) {
                const float* c = acc + mi*16 + ni*4;
                int r0 = m0 + wm*32 + mi*16 + g;
                int jj = n0 + wnw*32 + ni*8 + 2*tt;
                *(float2*)(po + (size_t)r0*ldN + jj)     = make_float2(c[0], c[1]);
                *(float2*)(po + (size_t)(r0+8)*ldN + jj) = make_float2(c[2], c[3]);
            }
    }
}

__global__ void split_x_kernel(const float* __restrict__ x) {
    int i = blockIdx.x * 256 + threadIdx.x;
    float v = x[i];
    __nv_bfloat16 h = __float2bfloat16(v);
    g_a_hi[i] = h;
    g_a_lo[i] = __float2bfloat16(v - __bfloat162float(h));
}

__global__ void reduce_split_kernel(float* __restrict__ out, int final_layer) {
    int i = blockIdx.x * 256 + threadIdx.x;
    float s = g_part[i] + g_part[i + NELEM_A] + g_part[i + 2*NELEM_A] + g_part[i + 3*NELEM_A];
    if (final_layer) {
        out[i] = s;
    } else {
        __nv_bfloat16 h = __float2bfloat16(s);
        g_a_hi[i] = h;
        g_a_lo[i] = __float2bfloat16(s - __bfloat162float(h));
    }
}

extern "C" void kernel_launch(void* const* d_in, const int* in_sizes, int n_in,
                              void* d_out, int out_size) {
    const float* x  = (const float*)d_in[0];
    const int*   gp = (const int*)d_in[1];
    const float* gs = (const float*)d_in[2];
    const int*   up = (const int*)d_in[3];
    const float* us = (const float*)d_in[4];
    const int*   dp = (const int*)d_in[5];
    const float* ds = (const float*)d_in[6];
    float* out = (float*)d_out;

    cudaFuncSetAttribute(gemm_kernel, cudaFuncAttributeMaxDynamicSharedMemorySize, GEMM_SMEM);

    void *p_ah, *p_al, *p_th, *p_tl, *p_g, *p_part;
    cudaGetSymbolAddress(&p_ah, g_a_hi);
    cudaGetSymbolAddress(&p_al, g_a_lo);
    cudaGetSymbolAddress(&p_th, g_t_hi);
    cudaGetSymbolAddress(&p_tl, g_t_lo);
    cudaGetSymbolAddress(&p_g, g_gate);
    cudaGetSymbolAddress(&p_part, g_part);

    split_x_kernel<<<NELEM_A/256, 256>>>(x);

    for (int l = 0; l < 18; ++l) {
        const size_t woff  = (size_t)l * MLP * (HID/2);
        const size_t soff  = (size_t)l * MLP * (HID/32);
        const size_t dwoff = (size_t)l * HID * (MLP/2);
        const size_t dsoff = (size_t)l * HID * (MLP/32);

        gemm_kernel<<<dim3(MLP/128, 2, 1), 512, GEMM_SMEM>>>(
            gp + woff, gs + soff,
            (const __nv_bfloat16*)p_ah, (const __nv_bfloat16*)p_al,
            (float*)p_g, HID, MLP, 0, nullptr, nullptr, nullptr);
        gemm_kernel<<<dim3(MLP/128, 2, 1), 512, GEMM_SMEM>>>(
            up + woff, us + soff,
            (const __nv_bfloat16*)p_ah, (const __nv_bfloat16*)p_al,
            nullptr, HID, MLP, 1, (const float*)p_g,
            (__nv_bfloat16*)p_th, (__nv_bfloat16*)p_tl);
        gemm_kernel<<<dim3(HID/128, 2, 4), 512, GEMM_SMEM>>>(
            dp + dwoff, ds + dsoff,
            (const __nv_bfloat16*)p_th, (const __nv_bfloat16*)p_tl,
            (float*)p_part, MLP, HID, 0, nullptr, nullptr, nullptr);
        reduce_split_kernel<<<NELEM_A/256, 256>>>(out, l == 17 ? 1 : 0);
    }
}